// round 13
// baseline (speedup 1.0000x reference)
#include <cuda_runtime.h>
#include <cstdint>

#define SEQ   512
#define BATCH 64
#define H     1024
#define H3    3072
#define VOCAB 32000
#define NCTA  128

// ---------------- device scratch (no cudaMalloc allowed) ----------------
__device__ float    g_gi[(size_t)SEQ * BATCH * H3];  // encoded @ W_ih (no bias)
__device__ float    g_h[BATCH * H];                  // final h (for dec only)
__device__ unsigned g_htf[3][BATCH * H];             // h ring buffer (tf32 bits)
__device__ unsigned g_flags[NCTA];                   // per-CTA completed-step counters
__device__ unsigned g_emb_tf[(size_t)VOCAB * H];     // emb pre-converted to tf32 bits
__device__ unsigned g_wih_tf[(size_t)H * H3];        // W_ih pre-converted to tf32 bits

// ---------------- helpers ----------------
__device__ __forceinline__ unsigned f2tf(float x) {
    unsigned r;
    asm("cvt.rna.tf32.f32 %0, %1;" : "=r"(r) : "f"(x));
    return r;
}

__device__ __forceinline__ void mma8(float c[4], const unsigned a[4],
                                     unsigned b0, unsigned b1) {
    asm volatile(
        "mma.sync.aligned.m16n8k8.row.col.f32.tf32.tf32.f32 "
        "{%0,%1,%2,%3},{%4,%5,%6,%7},{%8,%9},{%0,%1,%2,%3};"
        : "+f"(c[0]), "+f"(c[1]), "+f"(c[2]), "+f"(c[3])
        : "r"(a[0]), "r"(a[1]), "r"(a[2]), "r"(a[3]), "r"(b0), "r"(b1));
}

#define CP_ASYNC16(dst, src) \
    asm volatile("cp.async.cg.shared.global [%0], [%1], 16;" :: "r"(dst), "l"(src))
#define CP_COMMIT()  asm volatile("cp.async.commit_group;" ::: "memory")
#define CP_WAIT(n)   asm volatile("cp.async.wait_group %0;" :: "n"(n) : "memory")

__device__ __forceinline__ unsigned ld_acquire(const unsigned* p) {
    unsigned v;
    asm volatile("ld.acquire.gpu.u32 %0, [%1];" : "=r"(v) : "l"(p) : "memory");
    return v;
}
__device__ __forceinline__ void st_release(unsigned* p, unsigned v) {
    asm volatile("st.release.gpu.u32 [%0], %1;" :: "l"(p), "r"(v) : "memory");
}

// wait until 4 consecutive producer flags reach tgt (acquire loads pipeline)
__device__ __forceinline__ void wait_flags4(const unsigned* f, unsigned tgt) {
    for (;;) {
        unsigned v0 = ld_acquire(f + 0);
        unsigned v1 = ld_acquire(f + 1);
        unsigned v2 = ld_acquire(f + 2);
        unsigned v3 = ld_acquire(f + 3);
        if (v0 >= tgt && v1 >= tgt && v2 >= tgt && v3 >= tgt) return;
    }
}

__device__ __forceinline__ float sigm(float x) { return 1.0f / (1.0f + __expf(-x)); }
__device__ __forceinline__ float tanh_fast(float x) {
    float e = __expf(2.0f * x);
    return 1.0f - 2.0f / (e + 1.0f);
}

// ---------------- K0: init ----------------
__global__ void init_kernel() {
    int i = blockIdx.x * blockDim.x + threadIdx.x;
    if (i < BATCH * H) g_htf[0][i] = 0u;
    if (i < NCTA) g_flags[i] = 0u;
}

// ---------------- K0b: pre-convert emb / W_ih to tf32 bits ----------------
__global__ void conv_emb_kernel(const float* __restrict__ emb) {
    size_t i = ((size_t)blockIdx.x * blockDim.x + threadIdx.x) * 4;
    if (i < (size_t)VOCAB * H) {
        float4 v = *(const float4*)(emb + i);
        uint4 o;
        o.x = f2tf(v.x); o.y = f2tf(v.y); o.z = f2tf(v.z); o.w = f2tf(v.w);
        *(uint4*)(g_emb_tf + i) = o;
    }
}
__global__ void conv_wih_kernel(const float* __restrict__ W_ih) {
    size_t i = ((size_t)blockIdx.x * blockDim.x + threadIdx.x) * 4;
    if (i < (size_t)H * H3) {
        float4 v = *(const float4*)(W_ih + i);
        uint4 o;
        o.x = f2tf(v.x); o.y = f2tf(v.y); o.z = f2tf(v.z); o.w = f2tf(v.w);
        *(uint4*)(g_wih_tf + i) = o;
    }
}

// ---------------- K1: fused gather + gi GEMM (R10, untouched) ----------------
#define GI_AS_BUF (128 * 36)
#define GI_BS_BUF (32 * 136)
#define GI_SMEM_BYTES ((2 * GI_AS_BUF + 2 * GI_BS_BUF) * 4)

__global__ void __launch_bounds__(256) gi_kernel(const int* __restrict__ ids) {
    extern __shared__ unsigned gsm[];
    unsigned* As = gsm;                     // [2][128][36]
    unsigned* Bs = gsm + 2 * GI_AS_BUF;     // [2][32][136]
    __shared__ int ids_s[128];

    const int nb = blockIdx.x, mb = blockIdx.y;
    const int tid = threadIdx.x;
    const int w = tid >> 5, lane = tid & 31;
    const int wm = w >> 2, wn = w & 3;
    const int gid = lane >> 2, tig = lane & 3;

    if (tid < 128) ids_s[tid] = ids[mb * 128 + tid];
    __syncthreads();

    const unsigned as_smem = (unsigned)__cvta_generic_to_shared(As);
    const unsigned bs_smem = (unsigned)__cvta_generic_to_shared(Bs);

    const int a_row0 = tid >> 3;
    const int a_c0 = (tid & 7) * 4;
    const int b_r0 = tid >> 5;
    const int b_c0 = (tid & 31) * 4;

    auto stageA = [&](int buf, int kt) {
#pragma unroll
        for (int rep = 0; rep < 4; rep++) {
            int row = rep * 32 + a_row0;
            const unsigned* src = g_emb_tf + (size_t)ids_s[row] * H + kt + a_c0;
            CP_ASYNC16(as_smem + (unsigned)(buf * GI_AS_BUF + row * 36 + a_c0) * 4u, src);
        }
    };
    auto stageB = [&](int buf, int kt) {
#pragma unroll
        for (int rep = 0; rep < 4; rep++) {
            int r = rep * 8 + b_r0;
            const unsigned* src = g_wih_tf + (size_t)(kt + r) * H3 + nb * 128 + b_c0;
            CP_ASYNC16(bs_smem + (unsigned)(buf * GI_BS_BUF + r * 136 + b_c0) * 4u, src);
        }
    };

    float acc[4][4][4];
#pragma unroll
    for (int i = 0; i < 4; i++)
#pragma unroll
        for (int j = 0; j < 4; j++)
#pragma unroll
            for (int k = 0; k < 4; k++) acc[i][j][k] = 0.0f;

    stageA(0, 0); stageB(0, 0); CP_COMMIT();

    for (int t = 0; t < 32; t++) {
        const int buf = t & 1;
        __syncthreads();
        if (t < 31) {
            stageA(buf ^ 1, (t + 1) * 32);
            stageB(buf ^ 1, (t + 1) * 32);
            CP_COMMIT();
            CP_WAIT(1);
        } else {
            CP_WAIT(0);
        }
        __syncthreads();

        const unsigned* Ab = As + buf * GI_AS_BUF;
        const unsigned* Bb = Bs + buf * GI_BS_BUF;
#pragma unroll
        for (int ks = 0; ks < 32; ks += 8) {
            unsigned a[4][4];
#pragma unroll
            for (int mt = 0; mt < 4; mt++) {
                int rb = wm * 64 + mt * 16;
                a[mt][0] = Ab[(rb + gid) * 36 + ks + tig];
                a[mt][1] = Ab[(rb + gid + 8) * 36 + ks + tig];
                a[mt][2] = Ab[(rb + gid) * 36 + ks + tig + 4];
                a[mt][3] = Ab[(rb + gid + 8) * 36 + ks + tig + 4];
            }
#pragma unroll
            for (int nt = 0; nt < 4; nt++) {
                unsigned b0 = Bb[(ks + tig) * 136 + wn * 32 + nt * 8 + gid];
                unsigned b1 = Bb[(ks + tig + 4) * 136 + wn * 32 + nt * 8 + gid];
#pragma unroll
                for (int mt = 0; mt < 4; mt++) mma8(acc[mt][nt], a[mt], b0, b1);
            }
        }
    }

    size_t mrow0 = (size_t)mb * 128 + wm * 64;
    int colbase = nb * 128 + wn * 32;
#pragma unroll
    for (int mt = 0; mt < 4; mt++) {
        size_t m0 = mrow0 + mt * 16 + gid;
#pragma unroll
        for (int nt = 0; nt < 4; nt++) {
            int col = colbase + nt * 8 + tig * 2;
            *(float2*)(g_gi + m0 * H3 + col) = make_float2(acc[mt][nt][0], acc[mt][nt][1]);
            *(float2*)(g_gi + (m0 + 8) * H3 + col) = make_float2(acc[mt][nt][2], acc[mt][nt][3]);
        }
    }
}

// ---------------- K2: persistent GRU recurrence (dataflow flags, no global barrier) ----------------
// 128 CTAs x 256 threads. CTA c owns cols [c*8, c*8+8) of gates (r,z,n).
// FROZEN k-loop (R5/R10): warps 4m x 2kh, 32-col tiles, depth-4 cp.async ring.
// h in registers (R12). NEW: global barrier replaced by per-CTA dataflow flags:
// staging tile p waits only on the 4 producer CTAs of its 32 columns (flag>=s);
// 3-deep htf ring makes write-after-read safe (a CTA at step s has transitively
// observed flags>=s from all CTAs => everyone finished step s-2 reads of the
// buffer being overwritten).
#define WS_WORDS   (1024 * 24)
#define AS_WORDS_W 576
#define N_BUF      4
#define AS_WORDS   (8 * N_BUF * AS_WORDS_W)
#define GH_WORDS   (2 * 64 * 24)
#define SMEM_BYTES ((WS_WORDS + AS_WORDS + GH_WORDS) * 4)

__global__ void __launch_bounds__(256, 1) gru_persist_kernel(
    const float* __restrict__ W_hh,
    const float* __restrict__ b_ih,
    const float* __restrict__ b_hh) {
    extern __shared__ unsigned sm[];
    unsigned* Ws = sm;                                  // [1024][24]
    unsigned* As = sm + WS_WORDS;                       // [warp][4][16*36]
    float* ghs = (float*)(sm + WS_WORDS + AS_WORDS);    // [kh][64][24]

    const int c = blockIdx.x;
    const int tid = threadIdx.x;
    const int w = tid >> 5, lane = tid & 31;
    const int gid = lane >> 2, tig = lane & 3;
    const int mt = w & 3, kh = w >> 2;

    const unsigned as_base =
        (unsigned)__cvta_generic_to_shared(As + w * N_BUF * AS_WORDS_W);
    const int lr = lane >> 3;            // 0..3
    const int cw = (lane & 7) * 4;       // word col within 32

    // this warp's flag base: producers of tile p are CTAs kh*64 + p*4 .. +3
    const unsigned* flag_base = g_flags + kh * 64;

    // one-time W_hh slice preload (rna tf32)
    for (int idx = tid; idx < WS_WORDS; idx += 256) {
        int kk = idx / 24;
        int rem = idx - kk * 24;
        int g = rem >> 3, l = rem & 7;
        Ws[idx] = f2tf(W_hh[(size_t)kk * H3 + g * H + c * 8 + l]);
    }

    const int j = tid & 7;
    const int col = c * 8 + j;
    const int r0 = tid >> 3;
    const float bir = b_ih[col], biz = b_ih[H + col], bin = b_ih[2 * H + col];
    const float bhr = b_hh[col], bhz = b_hh[H + col], bhn = b_hh[2 * H + col];

    // register-resident hidden state
    float hp0 = 0.0f, hp1 = 0.0f;

    __syncthreads();

    int rbuf = 0;                        // s % 3
    for (int s = 0; s < SEQ; s++) {
        const unsigned* htf  = g_htf[rbuf];
        int wb = rbuf + 1; if (wb == 3) wb = 0;
        unsigned*       htfo = g_htf[wb];
        const float*    gi   = g_gi + (size_t)s * BATCH * H3;
        const unsigned  stgt = (unsigned)s;

        const unsigned* hsrc = htf + (mt * 16) * H + kh * 512 + cw;

        // stage pipeline: 3 tiles ahead (each gated on its 4 producer flags)
#pragma unroll
        for (int p = 0; p < 3; p++) {
            wait_flags4(flag_base + p * 4, stgt);
            unsigned dst = as_base + (unsigned)(p * AS_WORDS_W) * 4u;
#pragma unroll
            for (int rep = 0; rep < 4; rep++) {
                int row = rep * 4 + lr;
                CP_ASYNC16(dst + (unsigned)(row * 36 + cw) * 4u, hsrc + row * H + p * 32);
            }
            CP_COMMIT();
        }

        // gate-phase gi prefetch (independent; hides latency behind mma)
        const float* gp0 = gi + (size_t)r0 * H3;
        const float* gp1 = gi + (size_t)(r0 + 32) * H3;
        float ir0 = gp0[col], iz0 = gp0[H + col], in0 = gp0[2 * H + col];
        float ir1 = gp1[col], iz1 = gp1[H + col], in1 = gp1[2 * H + col];

        float acc[3][4];
#pragma unroll
        for (int i = 0; i < 3; i++)
#pragma unroll
            for (int q = 0; q < 4; q++) acc[i][q] = 0.0f;

#pragma unroll
        for (int it = 0; it < 16; it++) {
            if (it < 13) {
                int p = it + 3;
                wait_flags4(flag_base + p * 4, stgt);
                unsigned dst = as_base + (unsigned)((p & 3) * AS_WORDS_W) * 4u;
#pragma unroll
                for (int rep = 0; rep < 4; rep++) {
                    int row = rep * 4 + lr;
                    CP_ASYNC16(dst + (unsigned)(row * 36 + cw) * 4u,
                               hsrc + row * H + p * 32);
                }
                CP_COMMIT();
                CP_WAIT(3);
            } else if (it == 13) CP_WAIT(2);
            else if (it == 14) CP_WAIT(1);
            else CP_WAIT(0);
            __syncwarp();

            const unsigned* Ab = As + (w * N_BUF + (it & 3)) * AS_WORDS_W;
            const int kbase = kh * 512 + it * 32;
#pragma unroll
            for (int ks = 0; ks < 32; ks += 8) {
                unsigned a[4];
                a[0] = Ab[gid * 36 + ks + tig];
                a[1] = Ab[(gid + 8) * 36 + ks + tig];
                a[2] = Ab[gid * 36 + ks + tig + 4];
                a[3] = Ab[(gid + 8) * 36 + ks + tig + 4];
                const int kr = (kbase + ks + tig) * 24;
#pragma unroll
                for (int nt = 0; nt < 3; nt++) {
                    unsigned b0 = Ws[kr + nt * 8 + gid];
                    unsigned b1 = Ws[kr + 96 + nt * 8 + gid];
                    mma8(acc[nt], a, b0, b1);
                }
            }
        }

        // reduce the two k-halves via smem
        {
            int rr = mt * 16 + gid;
            float* gh = ghs + kh * (64 * 24);
#pragma unroll
            for (int nt = 0; nt < 3; nt++) {
                gh[rr * 24 + nt * 8 + tig * 2 + 0] = acc[nt][0];
                gh[rr * 24 + nt * 8 + tig * 2 + 1] = acc[nt][1];
                gh[(rr + 8) * 24 + nt * 8 + tig * 2 + 0] = acc[nt][2];
                gh[(rr + 8) * 24 + nt * 8 + tig * 2 + 1] = acc[nt][3];
            }
        }
        __syncthreads();

        // gate math: rows r0 and r0+32, column j (h carried in registers)
        {
            float ghr = ghs[r0 * 24 + j] + ghs[64 * 24 + r0 * 24 + j] + bhr;
            float ghz = ghs[r0 * 24 + 8 + j] + ghs[64 * 24 + r0 * 24 + 8 + j] + bhz;
            float ghn = ghs[r0 * 24 + 16 + j] + ghs[64 * 24 + r0 * 24 + 16 + j] + bhn;
            float r = sigm(ir0 + bir + ghr);
            float z = sigm(iz0 + biz + ghz);
            float n = tanh_fast(in0 + bin + r * ghn);
            hp0 = (1.0f - z) * n + z * hp0;
            htfo[r0 * H + col] = f2tf(hp0);

            int r1 = r0 + 32;
            ghr = ghs[r1 * 24 + j] + ghs[64 * 24 + r1 * 24 + j] + bhr;
            ghz = ghs[r1 * 24 + 8 + j] + ghs[64 * 24 + r1 * 24 + 8 + j] + bhz;
            ghn = ghs[r1 * 24 + 16 + j] + ghs[64 * 24 + r1 * 24 + 16 + j] + bhn;
            r = sigm(ir1 + bir + ghr);
            z = sigm(iz1 + biz + ghz);
            n = tanh_fast(in1 + bin + r * ghn);
            hp1 = (1.0f - z) * n + z * hp1;
            htfo[r1 * H + col] = f2tf(hp1);
        }

        // publish: all htfo writes done (ordered by syncthreads), then release flag
        __syncthreads();
        if (tid == 0) st_release(&g_flags[c], (unsigned)s + 1u);

        rbuf = wb;
    }

    // publish final h (fp32, full precision) for the dec kernel
    g_h[r0 * H + col] = hp0;
    g_h[(r0 + 32) * H + col] = hp1;
}

// ---------------- K3: decode + fc (8-way k-split, 1024 threads) ----------------
__global__ void __launch_bounds__(1024) dec_kernel(
    const float* __restrict__ W_dec, const float* __restrict__ b_dec,
    const float* __restrict__ W_fc, const float* __restrict__ b_fc,
    float* __restrict__ out) {
    int b = blockIdx.x;
    int tid = threadIdx.x;
    __shared__ float hs[H];
    __shared__ float part[8][100];
    __shared__ float ds[100];
    const float* hrow = g_h + b * H;
    for (int i = tid; i < H; i += 1024) hs[i] = hrow[i];
    __syncthreads();

    int o = tid & 127;
    int sp = tid >> 7;                    // 0..7 k-split
    if (o < 100) {
        float a0 = 0.0f, a1 = 0.0f, a2 = 0.0f, a3 = 0.0f;
        int kbase = sp * 128;
        const float* wp = W_dec + (size_t)kbase * 100 + o;
#pragma unroll 4
        for (int kk = 0; kk < 128; kk += 8) {
            a0 += hs[kbase + kk + 0] * wp[(kk + 0) * 100];
            a1 += hs[kbase + kk + 1] * wp[(kk + 1) * 100];
            a2 += hs[kbase + kk + 2] * wp[(kk + 2) * 100];
            a3 += hs[kbase + kk + 3] * wp[(kk + 3) * 100];
            a0 += hs[kbase + kk + 4] * wp[(kk + 4) * 100];
            a1 += hs[kbase + kk + 5] * wp[(kk + 5) * 100];
            a2 += hs[kbase + kk + 6] * wp[(kk + 6) * 100];
            a3 += hs[kbase + kk + 7] * wp[(kk + 7) * 100];
        }
        part[sp][o] = (a0 + a1) + (a2 + a3);
    }
    __syncthreads();
    if (tid < 100) {
        float d = b_dec[tid];
#pragma unroll
        for (int p = 0; p < 8; p++) d += part[p][tid];
        ds[tid] = fmaxf(d, 0.0f);
    }
    __syncthreads();
    if (tid < 2) {
        float a = b_fc[tid];
        for (int jj = 0; jj < 100; jj++) a += ds[jj] * W_fc[jj * 2 + tid];
        out[b * 2 + tid] = a;
    }
}

// ---------------- launch ----------------
extern "C" void kernel_launch(void* const* d_in, const int* in_sizes, int n_in,
                              void* d_out, int out_size) {
    const int* ids = (const int*)d_in[0];
    const float* emb = (const float*)d_in[1];
    const float* W_ih = (const float*)d_in[2];
    const float* W_hh = (const float*)d_in[3];
    const float* b_ih = (const float*)d_in[4];
    const float* b_hh = (const float*)d_in[5];
    const float* W_dec = (const float*)d_in[6];
    const float* b_dec = (const float*)d_in[7];
    const float* W_fc = (const float*)d_in[8];
    const float* b_fc = (const float*)d_in[9];
    float* out = (float*)d_out;

    static bool attr_set = false;
    if (!attr_set) {
        cudaFuncSetAttribute(gru_persist_kernel,
                             cudaFuncAttributeMaxDynamicSharedMemorySize, SMEM_BYTES);
        cudaFuncSetAttribute(gi_kernel,
                             cudaFuncAttributeMaxDynamicSharedMemorySize, GI_SMEM_BYTES);
        attr_set = true;
    }

    init_kernel<<<256, 256>>>();

    conv_emb_kernel<<<(VOCAB * H / 4 + 255) / 256, 256>>>(emb);
    conv_wih_kernel<<<(H * H3 / 4 + 255) / 256, 256>>>(W_ih);

    dim3 g1(24, 256);
    gi_kernel<<<g1, 256, GI_SMEM_BYTES>>>(ids);

    gru_persist_kernel<<<NCTA, 256, SMEM_BYTES>>>(W_hh, b_ih, b_hh);

    dec_kernel<<<64, 1024>>>(W_dec, b_dec, W_fc, b_fc, out);
}

// round 14
// speedup vs baseline: 1.8695x; 1.8695x over previous
#include <cuda_runtime.h>
#include <cstdint>

#define SEQ   512
#define BATCH 64
#define H     1024
#define H3    3072
#define VOCAB 32000
#define NCTA  128

// ---------------- device scratch (no cudaMalloc allowed) ----------------
__device__ float    g_gi[(size_t)SEQ * BATCH * H3];  // encoded @ W_ih (no bias)
__device__ float    g_h[BATCH * H];                  // final h (for dec only)
__device__ unsigned g_htf[2][BATCH * H];             // h ping-pong (tf32 bits)
__device__ unsigned g_bar;                           // grid barrier arrive counter
__device__ unsigned g_emb_tf[(size_t)VOCAB * H];     // emb pre-converted to tf32 bits
__device__ unsigned g_wih_tf[(size_t)H * H3];        // W_ih pre-converted to tf32 bits

// ---------------- helpers ----------------
__device__ __forceinline__ unsigned f2tf(float x) {
    unsigned r;
    asm("cvt.rna.tf32.f32 %0, %1;" : "=r"(r) : "f"(x));
    return r;
}

__device__ __forceinline__ void mma8(float c[4], const unsigned a[4],
                                     unsigned b0, unsigned b1) {
    asm volatile(
        "mma.sync.aligned.m16n8k8.row.col.f32.tf32.tf32.f32 "
        "{%0,%1,%2,%3},{%4,%5,%6,%7},{%8,%9},{%0,%1,%2,%3};"
        : "+f"(c[0]), "+f"(c[1]), "+f"(c[2]), "+f"(c[3])
        : "r"(a[0]), "r"(a[1]), "r"(a[2]), "r"(a[3]), "r"(b0), "r"(b1));
}

#define CP_ASYNC16(dst, src) \
    asm volatile("cp.async.cg.shared.global [%0], [%1], 16;" :: "r"(dst), "l"(src))
#define CP_COMMIT()  asm volatile("cp.async.commit_group;" ::: "memory")
#define CP_WAIT(n)   asm volatile("cp.async.wait_group %0;" :: "n"(n) : "memory")

__device__ __forceinline__ void red_add_release(unsigned* p, unsigned v) {
    asm volatile("red.release.gpu.global.add.u32 [%0], %1;"
                 :: "l"(p), "r"(v) : "memory");
}
__device__ __forceinline__ unsigned ld_acquire(const unsigned* p) {
    unsigned v;
    asm volatile("ld.acquire.gpu.u32 %0, [%1];" : "=r"(v) : "l"(p) : "memory");
    return v;
}

__device__ __forceinline__ float sigm(float x) { return 1.0f / (1.0f + __expf(-x)); }
__device__ __forceinline__ float tanh_fast(float x) {
    float e = __expf(2.0f * x);
    return 1.0f - 2.0f / (e + 1.0f);
}

// ---------------- K0: init ----------------
__global__ void init_kernel() {
    int i = blockIdx.x * blockDim.x + threadIdx.x;
    if (i < BATCH * H) g_htf[0][i] = 0u;
    if (i == 0) g_bar = 0u;
}

// ---------------- K0b: pre-convert emb / W_ih to tf32 bits ----------------
__global__ void conv_emb_kernel(const float* __restrict__ emb) {
    size_t i = ((size_t)blockIdx.x * blockDim.x + threadIdx.x) * 4;
    if (i < (size_t)VOCAB * H) {
        float4 v = *(const float4*)(emb + i);
        uint4 o;
        o.x = f2tf(v.x); o.y = f2tf(v.y); o.z = f2tf(v.z); o.w = f2tf(v.w);
        *(uint4*)(g_emb_tf + i) = o;
    }
}
__global__ void conv_wih_kernel(const float* __restrict__ W_ih) {
    size_t i = ((size_t)blockIdx.x * blockDim.x + threadIdx.x) * 4;
    if (i < (size_t)H * H3) {
        float4 v = *(const float4*)(W_ih + i);
        uint4 o;
        o.x = f2tf(v.x); o.y = f2tf(v.y); o.z = f2tf(v.z); o.w = f2tf(v.w);
        *(uint4*)(g_wih_tf + i) = o;
    }
}

// ---------------- K1: fused gather + gi GEMM (R10 + occupancy 3) ----------------
#define GI_AS_BUF (128 * 36)
#define GI_BS_BUF (32 * 136)
#define GI_SMEM_BYTES ((2 * GI_AS_BUF + 2 * GI_BS_BUF) * 4)

__global__ void __launch_bounds__(256, 3) gi_kernel(const int* __restrict__ ids) {
    extern __shared__ unsigned gsm[];
    unsigned* As = gsm;                     // [2][128][36]
    unsigned* Bs = gsm + 2 * GI_AS_BUF;     // [2][32][136]
    __shared__ int ids_s[128];

    const int nb = blockIdx.x, mb = blockIdx.y;
    const int tid = threadIdx.x;
    const int w = tid >> 5, lane = tid & 31;
    const int wm = w >> 2, wn = w & 3;
    const int gid = lane >> 2, tig = lane & 3;

    if (tid < 128) ids_s[tid] = ids[mb * 128 + tid];
    __syncthreads();

    const unsigned as_smem = (unsigned)__cvta_generic_to_shared(As);
    const unsigned bs_smem = (unsigned)__cvta_generic_to_shared(Bs);

    const int a_row0 = tid >> 3;
    const int a_c0 = (tid & 7) * 4;
    const int b_r0 = tid >> 5;
    const int b_c0 = (tid & 31) * 4;

    auto stageA = [&](int buf, int kt) {
#pragma unroll
        for (int rep = 0; rep < 4; rep++) {
            int row = rep * 32 + a_row0;
            const unsigned* src = g_emb_tf + (size_t)ids_s[row] * H + kt + a_c0;
            CP_ASYNC16(as_smem + (unsigned)(buf * GI_AS_BUF + row * 36 + a_c0) * 4u, src);
        }
    };
    auto stageB = [&](int buf, int kt) {
#pragma unroll
        for (int rep = 0; rep < 4; rep++) {
            int r = rep * 8 + b_r0;
            const unsigned* src = g_wih_tf + (size_t)(kt + r) * H3 + nb * 128 + b_c0;
            CP_ASYNC16(bs_smem + (unsigned)(buf * GI_BS_BUF + r * 136 + b_c0) * 4u, src);
        }
    };

    float acc[4][4][4];
#pragma unroll
    for (int i = 0; i < 4; i++)
#pragma unroll
        for (int j = 0; j < 4; j++)
#pragma unroll
            for (int k = 0; k < 4; k++) acc[i][j][k] = 0.0f;

    stageA(0, 0); stageB(0, 0); CP_COMMIT();

    for (int t = 0; t < 32; t++) {
        const int buf = t & 1;
        __syncthreads();
        if (t < 31) {
            stageA(buf ^ 1, (t + 1) * 32);
            stageB(buf ^ 1, (t + 1) * 32);
            CP_COMMIT();
            CP_WAIT(1);
        } else {
            CP_WAIT(0);
        }
        __syncthreads();

        const unsigned* Ab = As + buf * GI_AS_BUF;
        const unsigned* Bb = Bs + buf * GI_BS_BUF;
#pragma unroll
        for (int ks = 0; ks < 32; ks += 8) {
            unsigned a[4][4];
#pragma unroll
            for (int mt = 0; mt < 4; mt++) {
                int rb = wm * 64 + mt * 16;
                a[mt][0] = Ab[(rb + gid) * 36 + ks + tig];
                a[mt][1] = Ab[(rb + gid + 8) * 36 + ks + tig];
                a[mt][2] = Ab[(rb + gid) * 36 + ks + tig + 4];
                a[mt][3] = Ab[(rb + gid + 8) * 36 + ks + tig + 4];
            }
#pragma unroll
            for (int nt = 0; nt < 4; nt++) {
                unsigned b0 = Bb[(ks + tig) * 136 + wn * 32 + nt * 8 + gid];
                unsigned b1 = Bb[(ks + tig + 4) * 136 + wn * 32 + nt * 8 + gid];
#pragma unroll
                for (int mt = 0; mt < 4; mt++) mma8(acc[mt][nt], a[mt], b0, b1);
            }
        }
    }

    size_t mrow0 = (size_t)mb * 128 + wm * 64;
    int colbase = nb * 128 + wn * 32;
#pragma unroll
    for (int mt = 0; mt < 4; mt++) {
        size_t m0 = mrow0 + mt * 16 + gid;
#pragma unroll
        for (int nt = 0; nt < 4; nt++) {
            int col = colbase + nt * 8 + tig * 2;
            *(float2*)(g_gi + m0 * H3 + col) = make_float2(acc[mt][nt][0], acc[mt][nt][1]);
            *(float2*)(g_gi + (m0 + 8) * H3 + col) = make_float2(acc[mt][nt][2], acc[mt][nt][3]);
        }
    }
}

// ---------------- K2: persistent GRU recurrence (R12, proven best, untouched
//                    except: final step skips htfo stores + barrier) ----------------
#define WS_WORDS   (1024 * 24)
#define AS_WORDS_W 576
#define N_BUF      4
#define AS_WORDS   (8 * N_BUF * AS_WORDS_W)
#define GH_WORDS   (2 * 64 * 24)
#define SMEM_BYTES ((WS_WORDS + AS_WORDS + GH_WORDS) * 4)

__global__ void __launch_bounds__(256, 1) gru_persist_kernel(
    const float* __restrict__ W_hh,
    const float* __restrict__ b_ih,
    const float* __restrict__ b_hh) {
    extern __shared__ unsigned sm[];
    unsigned* Ws = sm;                                  // [1024][24]
    unsigned* As = sm + WS_WORDS;                       // [warp][4][16*36]
    float* ghs = (float*)(sm + WS_WORDS + AS_WORDS);    // [kh][64][24]

    const int c = blockIdx.x;
    const int tid = threadIdx.x;
    const int w = tid >> 5, lane = tid & 31;
    const int gid = lane >> 2, tig = lane & 3;
    const int mt = w & 3, kh = w >> 2;

    const unsigned as_base =
        (unsigned)__cvta_generic_to_shared(As + w * N_BUF * AS_WORDS_W);
    const int lr = lane >> 3;            // 0..3
    const int cw = (lane & 7) * 4;       // word col within 32

    // one-time W_hh slice preload (rna tf32)
    for (int idx = tid; idx < WS_WORDS; idx += 256) {
        int kk = idx / 24;
        int rem = idx - kk * 24;
        int g = rem >> 3, l = rem & 7;
        Ws[idx] = f2tf(W_hh[(size_t)kk * H3 + g * H + c * 8 + l]);
    }

    const int j = tid & 7;
    const int col = c * 8 + j;
    const int r0 = tid >> 3;
    const float bir = b_ih[col], biz = b_ih[H + col], bin = b_ih[2 * H + col];
    const float bhr = b_hh[col], bhz = b_hh[H + col], bhn = b_hh[2 * H + col];

    // register-resident hidden state
    float hp0 = 0.0f, hp1 = 0.0f;

    __syncthreads();

    for (int s = 0; s < SEQ; s++) {
        const unsigned* htf  = g_htf[s & 1];
        unsigned*       htfo = g_htf[(s + 1) & 1];
        const float*    gi   = g_gi + (size_t)s * BATCH * H3;

        const unsigned* hsrc = htf + (mt * 16) * H + kh * 512 + cw;

        // stage pipeline: 3 tiles ahead
#pragma unroll
        for (int p = 0; p < 3; p++) {
            unsigned dst = as_base + (unsigned)(p * AS_WORDS_W) * 4u;
#pragma unroll
            for (int rep = 0; rep < 4; rep++) {
                int row = rep * 4 + lr;
                CP_ASYNC16(dst + (unsigned)(row * 36 + cw) * 4u, hsrc + row * H + p * 32);
            }
            CP_COMMIT();
        }

        // gate-phase gi prefetch (independent; hides latency behind mma)
        const float* gp0 = gi + (size_t)r0 * H3;
        const float* gp1 = gi + (size_t)(r0 + 32) * H3;
        float ir0 = gp0[col], iz0 = gp0[H + col], in0 = gp0[2 * H + col];
        float ir1 = gp1[col], iz1 = gp1[H + col], in1 = gp1[2 * H + col];

        float acc[3][4];
#pragma unroll
        for (int i = 0; i < 3; i++)
#pragma unroll
            for (int q = 0; q < 4; q++) acc[i][q] = 0.0f;

#pragma unroll
        for (int it = 0; it < 16; it++) {
            if (it < 13) {
                int p = it + 3;
                unsigned dst = as_base + (unsigned)((p & 3) * AS_WORDS_W) * 4u;
#pragma unroll
                for (int rep = 0; rep < 4; rep++) {
                    int row = rep * 4 + lr;
                    CP_ASYNC16(dst + (unsigned)(row * 36 + cw) * 4u,
                               hsrc + row * H + p * 32);
                }
                CP_COMMIT();
                CP_WAIT(3);
            } else if (it == 13) CP_WAIT(2);
            else if (it == 14) CP_WAIT(1);
            else CP_WAIT(0);
            __syncwarp();

            const unsigned* Ab = As + (w * N_BUF + (it & 3)) * AS_WORDS_W;
            const int kbase = kh * 512 + it * 32;
#pragma unroll
            for (int ks = 0; ks < 32; ks += 8) {
                unsigned a[4];
                a[0] = Ab[gid * 36 + ks + tig];
                a[1] = Ab[(gid + 8) * 36 + ks + tig];
                a[2] = Ab[gid * 36 + ks + tig + 4];
                a[3] = Ab[(gid + 8) * 36 + ks + tig + 4];
                const int kr = (kbase + ks + tig) * 24;
#pragma unroll
                for (int nt = 0; nt < 3; nt++) {
                    unsigned b0 = Ws[kr + nt * 8 + gid];
                    unsigned b1 = Ws[kr + 96 + nt * 8 + gid];
                    mma8(acc[nt], a, b0, b1);
                }
            }
        }

        // reduce the two k-halves via smem
        {
            int rr = mt * 16 + gid;
            float* gh = ghs + kh * (64 * 24);
#pragma unroll
            for (int nt = 0; nt < 3; nt++) {
                gh[rr * 24 + nt * 8 + tig * 2 + 0] = acc[nt][0];
                gh[rr * 24 + nt * 8 + tig * 2 + 1] = acc[nt][1];
                gh[(rr + 8) * 24 + nt * 8 + tig * 2 + 0] = acc[nt][2];
                gh[(rr + 8) * 24 + nt * 8 + tig * 2 + 1] = acc[nt][3];
            }
        }
        __syncthreads();

        // gate math: rows r0 and r0+32, column j (h carried in registers)
        const bool last = (s == SEQ - 1);
        {
            float ghr = ghs[r0 * 24 + j] + ghs[64 * 24 + r0 * 24 + j] + bhr;
            float ghz = ghs[r0 * 24 + 8 + j] + ghs[64 * 24 + r0 * 24 + 8 + j] + bhz;
            float ghn = ghs[r0 * 24 + 16 + j] + ghs[64 * 24 + r0 * 24 + 16 + j] + bhn;
            float r = sigm(ir0 + bir + ghr);
            float z = sigm(iz0 + biz + ghz);
            float n = tanh_fast(in0 + bin + r * ghn);
            hp0 = (1.0f - z) * n + z * hp0;
            if (!last) htfo[r0 * H + col] = f2tf(hp0);

            int r1 = r0 + 32;
            ghr = ghs[r1 * 24 + j] + ghs[64 * 24 + r1 * 24 + j] + bhr;
            ghz = ghs[r1 * 24 + 8 + j] + ghs[64 * 24 + r1 * 24 + 8 + j] + bhz;
            ghn = ghs[r1 * 24 + 16 + j] + ghs[64 * 24 + r1 * 24 + 16 + j] + bhn;
            r = sigm(ir1 + bir + ghr);
            z = sigm(iz1 + biz + ghz);
            n = tanh_fast(in1 + bin + r * ghn);
            hp1 = (1.0f - z) * n + z * hp1;
            if (!last) htfo[r1 * H + col] = f2tf(hp1);
        }

        if (!last) {
            // grid barrier: fire-and-forget arrival + direct counter poll
            __syncthreads();
            if (tid == 0) {
                unsigned tgt = (unsigned)(s + 1) * (unsigned)NCTA;
                red_add_release(&g_bar, 1u);
                while (ld_acquire(&g_bar) < tgt) {}
            }
            __syncthreads();
        }
    }

    // publish final h (fp32, full precision) for the dec kernel
    g_h[r0 * H + col] = hp0;
    g_h[(r0 + 32) * H + col] = hp1;
}

// ---------------- K3: decode + fc (8-way k-split, 1024 threads) ----------------
__global__ void __launch_bounds__(1024) dec_kernel(
    const float* __restrict__ W_dec, const float* __restrict__ b_dec,
    const float* __restrict__ W_fc, const float* __restrict__ b_fc,
    float* __restrict__ out) {
    int b = blockIdx.x;
    int tid = threadIdx.x;
    __shared__ float hs[H];
    __shared__ float part[8][100];
    __shared__ float ds[100];
    const float* hrow = g_h + b * H;
    for (int i = tid; i < H; i += 1024) hs[i] = hrow[i];
    __syncthreads();

    int o = tid & 127;
    int sp = tid >> 7;                    // 0..7 k-split
    if (o < 100) {
        float a0 = 0.0f, a1 = 0.0f, a2 = 0.0f, a3 = 0.0f;
        int kbase = sp * 128;
        const float* wp = W_dec + (size_t)kbase * 100 + o;
#pragma unroll 4
        for (int kk = 0; kk < 128; kk += 8) {
            a0 += hs[kbase + kk + 0] * wp[(kk + 0) * 100];
            a1 += hs[kbase + kk + 1] * wp[(kk + 1) * 100];
            a2 += hs[kbase + kk + 2] * wp[(kk + 2) * 100];
            a3 += hs[kbase + kk + 3] * wp[(kk + 3) * 100];
            a0 += hs[kbase + kk + 4] * wp[(kk + 4) * 100];
            a1 += hs[kbase + kk + 5] * wp[(kk + 5) * 100];
            a2 += hs[kbase + kk + 6] * wp[(kk + 6) * 100];
            a3 += hs[kbase + kk + 7] * wp[(kk + 7) * 100];
        }
        part[sp][o] = (a0 + a1) + (a2 + a3);
    }
    __syncthreads();
    if (tid < 100) {
        float d = b_dec[tid];
#pragma unroll
        for (int p = 0; p < 8; p++) d += part[p][tid];
        ds[tid] = fmaxf(d, 0.0f);
    }
    __syncthreads();
    if (tid < 2) {
        float a = b_fc[tid];
        for (int jj = 0; jj < 100; jj++) a += ds[jj] * W_fc[jj * 2 + tid];
        out[b * 2 + tid] = a;
    }
}

// ---------------- launch ----------------
extern "C" void kernel_launch(void* const* d_in, const int* in_sizes, int n_in,
                              void* d_out, int out_size) {
    const int* ids = (const int*)d_in[0];
    const float* emb = (const float*)d_in[1];
    const float* W_ih = (const float*)d_in[2];
    const float* W_hh = (const float*)d_in[3];
    const float* b_ih = (const float*)d_in[4];
    const float* b_hh = (const float*)d_in[5];
    const float* W_dec = (const float*)d_in[6];
    const float* b_dec = (const float*)d_in[7];
    const float* W_fc = (const float*)d_in[8];
    const float* b_fc = (const float*)d_in[9];
    float* out = (float*)d_out;

    static bool attr_set = false;
    if (!attr_set) {
        cudaFuncSetAttribute(gru_persist_kernel,
                             cudaFuncAttributeMaxDynamicSharedMemorySize, SMEM_BYTES);
        cudaFuncSetAttribute(gi_kernel,
                             cudaFuncAttributeMaxDynamicSharedMemorySize, GI_SMEM_BYTES);
        attr_set = true;
    }

    init_kernel<<<256, 256>>>();

    conv_emb_kernel<<<(VOCAB * H / 4 + 255) / 256, 256>>>(emb);
    conv_wih_kernel<<<(H * H3 / 4 + 255) / 256, 256>>>(W_ih);

    dim3 g1(24, 256);
    gi_kernel<<<g1, 256, GI_SMEM_BYTES>>>(ids);

    gru_persist_kernel<<<NCTA, 256, SMEM_BYTES>>>(W_hh, b_ih, b_hh);

    dec_kernel<<<64, 1024>>>(W_dec, b_dec, W_fc, b_fc, out);
}

// round 15
// speedup vs baseline: 2.3260x; 1.2442x over previous
#include <cuda_runtime.h>
#include <cstdint>

#define SEQ   512
#define BATCH 64
#define H     1024
#define H3    3072
#define VOCAB 32000
#define NCTA  128

// ---------------- device scratch (no cudaMalloc allowed) ----------------
__device__ float    g_gi[(size_t)SEQ * BATCH * H3];  // encoded @ W_ih (no bias)
__device__ float    g_h[BATCH * H];                  // final h (for dec only)
__device__ unsigned g_htf[2][BATCH * H];             // h ping-pong (tf32 bits)
__device__ unsigned g_bar;                           // grid barrier arrive counter
__device__ unsigned g_emb_tf[(size_t)VOCAB * H];     // emb pre-converted to tf32 bits
__device__ unsigned g_wih_tf[(size_t)H * H3];        // W_ih pre-converted to tf32 bits

// ---------------- helpers ----------------
__device__ __forceinline__ unsigned f2tf(float x) {
    unsigned r;
    asm("cvt.rna.tf32.f32 %0, %1;" : "=r"(r) : "f"(x));
    return r;
}

__device__ __forceinline__ void mma8(float c[4], const unsigned a[4],
                                     unsigned b0, unsigned b1) {
    asm volatile(
        "mma.sync.aligned.m16n8k8.row.col.f32.tf32.tf32.f32 "
        "{%0,%1,%2,%3},{%4,%5,%6,%7},{%8,%9},{%0,%1,%2,%3};"
        : "+f"(c[0]), "+f"(c[1]), "+f"(c[2]), "+f"(c[3])
        : "r"(a[0]), "r"(a[1]), "r"(a[2]), "r"(a[3]), "r"(b0), "r"(b1));
}

#define CP_ASYNC16(dst, src) \
    asm volatile("cp.async.cg.shared.global [%0], [%1], 16;" :: "r"(dst), "l"(src))
#define CP_COMMIT()  asm volatile("cp.async.commit_group;" ::: "memory")
#define CP_WAIT(n)   asm volatile("cp.async.wait_group %0;" :: "n"(n) : "memory")

__device__ __forceinline__ void red_add_release(unsigned* p, unsigned v) {
    asm volatile("red.release.gpu.global.add.u32 [%0], %1;"
                 :: "l"(p), "r"(v) : "memory");
}
__device__ __forceinline__ unsigned ld_acquire(const unsigned* p) {
    unsigned v;
    asm volatile("ld.acquire.gpu.u32 %0, [%1];" : "=r"(v) : "l"(p) : "memory");
    return v;
}

__device__ __forceinline__ float sigm(float x) { return 1.0f / (1.0f + __expf(-x)); }
__device__ __forceinline__ float tanh_fast(float x) {
    float e = __expf(2.0f * x);
    return 1.0f - 2.0f / (e + 1.0f);
}

// ---------------- K0: init ----------------
__global__ void init_kernel() {
    int i = blockIdx.x * blockDim.x + threadIdx.x;
    if (i < BATCH * H) g_htf[0][i] = 0u;
    if (i == 0) g_bar = 0u;
}

// ---------------- K0b: pre-convert emb / W_ih to tf32 bits ----------------
__global__ void conv_emb_kernel(const float* __restrict__ emb) {
    size_t i = ((size_t)blockIdx.x * blockDim.x + threadIdx.x) * 4;
    if (i < (size_t)VOCAB * H) {
        float4 v = *(const float4*)(emb + i);
        uint4 o;
        o.x = f2tf(v.x); o.y = f2tf(v.y); o.z = f2tf(v.z); o.w = f2tf(v.w);
        *(uint4*)(g_emb_tf + i) = o;
    }
}
__global__ void conv_wih_kernel(const float* __restrict__ W_ih) {
    size_t i = ((size_t)blockIdx.x * blockDim.x + threadIdx.x) * 4;
    if (i < (size_t)H * H3) {
        float4 v = *(const float4*)(W_ih + i);
        uint4 o;
        o.x = f2tf(v.x); o.y = f2tf(v.y); o.z = f2tf(v.z); o.w = f2tf(v.w);
        *(uint4*)(g_wih_tf + i) = o;
    }
}

// ---------------- K1: fused gather + gi GEMM (R12 exact: NO min-blocks cap) ----------------
#define GI_AS_BUF (128 * 36)
#define GI_BS_BUF (32 * 136)
#define GI_SMEM_BYTES ((2 * GI_AS_BUF + 2 * GI_BS_BUF) * 4)

__global__ void __launch_bounds__(256) gi_kernel(const int* __restrict__ ids) {
    extern __shared__ unsigned gsm[];
    unsigned* As = gsm;                     // [2][128][36]
    unsigned* Bs = gsm + 2 * GI_AS_BUF;     // [2][32][136]
    __shared__ int ids_s[128];

    const int nb = blockIdx.x, mb = blockIdx.y;
    const int tid = threadIdx.x;
    const int w = tid >> 5, lane = tid & 31;
    const int wm = w >> 2, wn = w & 3;
    const int gid = lane >> 2, tig = lane & 3;

    if (tid < 128) ids_s[tid] = ids[mb * 128 + tid];
    __syncthreads();

    const unsigned as_smem = (unsigned)__cvta_generic_to_shared(As);
    const unsigned bs_smem = (unsigned)__cvta_generic_to_shared(Bs);

    const int a_row0 = tid >> 3;
    const int a_c0 = (tid & 7) * 4;
    const int b_r0 = tid >> 5;
    const int b_c0 = (tid & 31) * 4;

    auto stageA = [&](int buf, int kt) {
#pragma unroll
        for (int rep = 0; rep < 4; rep++) {
            int row = rep * 32 + a_row0;
            const unsigned* src = g_emb_tf + (size_t)ids_s[row] * H + kt + a_c0;
            CP_ASYNC16(as_smem + (unsigned)(buf * GI_AS_BUF + row * 36 + a_c0) * 4u, src);
        }
    };
    auto stageB = [&](int buf, int kt) {
#pragma unroll
        for (int rep = 0; rep < 4; rep++) {
            int r = rep * 8 + b_r0;
            const unsigned* src = g_wih_tf + (size_t)(kt + r) * H3 + nb * 128 + b_c0;
            CP_ASYNC16(bs_smem + (unsigned)(buf * GI_BS_BUF + r * 136 + b_c0) * 4u, src);
        }
    };

    float acc[4][4][4];
#pragma unroll
    for (int i = 0; i < 4; i++)
#pragma unroll
        for (int j = 0; j < 4; j++)
#pragma unroll
            for (int k = 0; k < 4; k++) acc[i][j][k] = 0.0f;

    stageA(0, 0); stageB(0, 0); CP_COMMIT();

    for (int t = 0; t < 32; t++) {
        const int buf = t & 1;
        __syncthreads();
        if (t < 31) {
            stageA(buf ^ 1, (t + 1) * 32);
            stageB(buf ^ 1, (t + 1) * 32);
            CP_COMMIT();
            CP_WAIT(1);
        } else {
            CP_WAIT(0);
        }
        __syncthreads();

        const unsigned* Ab = As + buf * GI_AS_BUF;
        const unsigned* Bb = Bs + buf * GI_BS_BUF;
#pragma unroll
        for (int ks = 0; ks < 32; ks += 8) {
            unsigned a[4][4];
#pragma unroll
            for (int mt = 0; mt < 4; mt++) {
                int rb = wm * 64 + mt * 16;
                a[mt][0] = Ab[(rb + gid) * 36 + ks + tig];
                a[mt][1] = Ab[(rb + gid + 8) * 36 + ks + tig];
                a[mt][2] = Ab[(rb + gid) * 36 + ks + tig + 4];
                a[mt][3] = Ab[(rb + gid + 8) * 36 + ks + tig + 4];
            }
#pragma unroll
            for (int nt = 0; nt < 4; nt++) {
                unsigned b0 = Bb[(ks + tig) * 136 + wn * 32 + nt * 8 + gid];
                unsigned b1 = Bb[(ks + tig + 4) * 136 + wn * 32 + nt * 8 + gid];
#pragma unroll
                for (int mt = 0; mt < 4; mt++) mma8(acc[mt][nt], a[mt], b0, b1);
            }
        }
    }

    size_t mrow0 = (size_t)mb * 128 + wm * 64;
    int colbase = nb * 128 + wn * 32;
#pragma unroll
    for (int mt = 0; mt < 4; mt++) {
        size_t m0 = mrow0 + mt * 16 + gid;
#pragma unroll
        for (int nt = 0; nt < 4; nt++) {
            int col = colbase + nt * 8 + tig * 2;
            *(float2*)(g_gi + m0 * H3 + col) = make_float2(acc[mt][nt][0], acc[mt][nt][1]);
            *(float2*)(g_gi + (m0 + 8) * H3 + col) = make_float2(acc[mt][nt][2], acc[mt][nt][3]);
        }
    }
}

// ---------------- K2: persistent GRU recurrence (R12 + final-step dead-work skip) ----------------
#define WS_WORDS   (1024 * 24)
#define AS_WORDS_W 576
#define N_BUF      4
#define AS_WORDS   (8 * N_BUF * AS_WORDS_W)
#define GH_WORDS   (2 * 64 * 24)
#define SMEM_BYTES ((WS_WORDS + AS_WORDS + GH_WORDS) * 4)

__global__ void __launch_bounds__(256, 1) gru_persist_kernel(
    const float* __restrict__ W_hh,
    const float* __restrict__ b_ih,
    const float* __restrict__ b_hh) {
    extern __shared__ unsigned sm[];
    unsigned* Ws = sm;                                  // [1024][24]
    unsigned* As = sm + WS_WORDS;                       // [warp][4][16*36]
    float* ghs = (float*)(sm + WS_WORDS + AS_WORDS);    // [kh][64][24]

    const int c = blockIdx.x;
    const int tid = threadIdx.x;
    const int w = tid >> 5, lane = tid & 31;
    const int gid = lane >> 2, tig = lane & 3;
    const int mt = w & 3, kh = w >> 2;

    const unsigned as_base =
        (unsigned)__cvta_generic_to_shared(As + w * N_BUF * AS_WORDS_W);
    const int lr = lane >> 3;            // 0..3
    const int cw = (lane & 7) * 4;       // word col within 32

    // one-time W_hh slice preload (rna tf32)
    for (int idx = tid; idx < WS_WORDS; idx += 256) {
        int kk = idx / 24;
        int rem = idx - kk * 24;
        int g = rem >> 3, l = rem & 7;
        Ws[idx] = f2tf(W_hh[(size_t)kk * H3 + g * H + c * 8 + l]);
    }

    const int j = tid & 7;
    const int col = c * 8 + j;
    const int r0 = tid >> 3;
    const float bir = b_ih[col], biz = b_ih[H + col], bin = b_ih[2 * H + col];
    const float bhr = b_hh[col], bhz = b_hh[H + col], bhn = b_hh[2 * H + col];

    // register-resident hidden state
    float hp0 = 0.0f, hp1 = 0.0f;

    __syncthreads();

    for (int s = 0; s < SEQ; s++) {
        const unsigned* htf  = g_htf[s & 1];
        unsigned*       htfo = g_htf[(s + 1) & 1];
        const float*    gi   = g_gi + (size_t)s * BATCH * H3;

        const unsigned* hsrc = htf + (mt * 16) * H + kh * 512 + cw;

        // stage pipeline: 3 tiles ahead
#pragma unroll
        for (int p = 0; p < 3; p++) {
            unsigned dst = as_base + (unsigned)(p * AS_WORDS_W) * 4u;
#pragma unroll
            for (int rep = 0; rep < 4; rep++) {
                int row = rep * 4 + lr;
                CP_ASYNC16(dst + (unsigned)(row * 36 + cw) * 4u, hsrc + row * H + p * 32);
            }
            CP_COMMIT();
        }

        // gate-phase gi prefetch (independent; hides latency behind mma)
        const float* gp0 = gi + (size_t)r0 * H3;
        const float* gp1 = gi + (size_t)(r0 + 32) * H3;
        float ir0 = gp0[col], iz0 = gp0[H + col], in0 = gp0[2 * H + col];
        float ir1 = gp1[col], iz1 = gp1[H + col], in1 = gp1[2 * H + col];

        float acc[3][4];
#pragma unroll
        for (int i = 0; i < 3; i++)
#pragma unroll
            for (int q = 0; q < 4; q++) acc[i][q] = 0.0f;

#pragma unroll
        for (int it = 0; it < 16; it++) {
            if (it < 13) {
                int p = it + 3;
                unsigned dst = as_base + (unsigned)((p & 3) * AS_WORDS_W) * 4u;
#pragma unroll
                for (int rep = 0; rep < 4; rep++) {
                    int row = rep * 4 + lr;
                    CP_ASYNC16(dst + (unsigned)(row * 36 + cw) * 4u,
                               hsrc + row * H + p * 32);
                }
                CP_COMMIT();
                CP_WAIT(3);
            } else if (it == 13) CP_WAIT(2);
            else if (it == 14) CP_WAIT(1);
            else CP_WAIT(0);
            __syncwarp();

            const unsigned* Ab = As + (w * N_BUF + (it & 3)) * AS_WORDS_W;
            const int kbase = kh * 512 + it * 32;
#pragma unroll
            for (int ks = 0; ks < 32; ks += 8) {
                unsigned a[4];
                a[0] = Ab[gid * 36 + ks + tig];
                a[1] = Ab[(gid + 8) * 36 + ks + tig];
                a[2] = Ab[gid * 36 + ks + tig + 4];
                a[3] = Ab[(gid + 8) * 36 + ks + tig + 4];
                const int kr = (kbase + ks + tig) * 24;
#pragma unroll
                for (int nt = 0; nt < 3; nt++) {
                    unsigned b0 = Ws[kr + nt * 8 + gid];
                    unsigned b1 = Ws[kr + 96 + nt * 8 + gid];
                    mma8(acc[nt], a, b0, b1);
                }
            }
        }

        // reduce the two k-halves via smem
        {
            int rr = mt * 16 + gid;
            float* gh = ghs + kh * (64 * 24);
#pragma unroll
            for (int nt = 0; nt < 3; nt++) {
                gh[rr * 24 + nt * 8 + tig * 2 + 0] = acc[nt][0];
                gh[rr * 24 + nt * 8 + tig * 2 + 1] = acc[nt][1];
                gh[(rr + 8) * 24 + nt * 8 + tig * 2 + 0] = acc[nt][2];
                gh[(rr + 8) * 24 + nt * 8 + tig * 2 + 1] = acc[nt][3];
            }
        }
        __syncthreads();

        // gate math: rows r0 and r0+32, column j (h carried in registers)
        const bool last = (s == SEQ - 1);
        {
            float ghr = ghs[r0 * 24 + j] + ghs[64 * 24 + r0 * 24 + j] + bhr;
            float ghz = ghs[r0 * 24 + 8 + j] + ghs[64 * 24 + r0 * 24 + 8 + j] + bhz;
            float ghn = ghs[r0 * 24 + 16 + j] + ghs[64 * 24 + r0 * 24 + 16 + j] + bhn;
            float r = sigm(ir0 + bir + ghr);
            float z = sigm(iz0 + biz + ghz);
            float n = tanh_fast(in0 + bin + r * ghn);
            hp0 = (1.0f - z) * n + z * hp0;
            if (!last) htfo[r0 * H + col] = f2tf(hp0);

            int r1 = r0 + 32;
            ghr = ghs[r1 * 24 + j] + ghs[64 * 24 + r1 * 24 + j] + bhr;
            ghz = ghs[r1 * 24 + 8 + j] + ghs[64 * 24 + r1 * 24 + 8 + j] + bhz;
            ghn = ghs[r1 * 24 + 16 + j] + ghs[64 * 24 + r1 * 24 + 16 + j] + bhn;
            r = sigm(ir1 + bir + ghr);
            z = sigm(iz1 + biz + ghz);
            n = tanh_fast(in1 + bin + r * ghn);
            hp1 = (1.0f - z) * n + z * hp1;
            if (!last) htfo[r1 * H + col] = f2tf(hp1);
        }

        if (!last) {
            // grid barrier: fire-and-forget arrival + direct counter poll
            __syncthreads();
            if (tid == 0) {
                unsigned tgt = (unsigned)(s + 1) * (unsigned)NCTA;
                red_add_release(&g_bar, 1u);
                while (ld_acquire(&g_bar) < tgt) {}
            }
            __syncthreads();
        }
    }

    // publish final h (fp32, full precision) for the dec kernel
    g_h[r0 * H + col] = hp0;
    g_h[(r0 + 32) * H + col] = hp1;
}

// ---------------- K3: decode + fc (8-way k-split, 1024 threads) ----------------
__global__ void __launch_bounds__(1024) dec_kernel(
    const float* __restrict__ W_dec, const float* __restrict__ b_dec,
    const float* __restrict__ W_fc, const float* __restrict__ b_fc,
    float* __restrict__ out) {
    int b = blockIdx.x;
    int tid = threadIdx.x;
    __shared__ float hs[H];
    __shared__ float part[8][100];
    __shared__ float ds[100];
    const float* hrow = g_h + b * H;
    for (int i = tid; i < H; i += 1024) hs[i] = hrow[i];
    __syncthreads();

    int o = tid & 127;
    int sp = tid >> 7;                    // 0..7 k-split
    if (o < 100) {
        float a0 = 0.0f, a1 = 0.0f, a2 = 0.0f, a3 = 0.0f;
        int kbase = sp * 128;
        const float* wp = W_dec + (size_t)kbase * 100 + o;
#pragma unroll 4
        for (int kk = 0; kk < 128; kk += 8) {
            a0 += hs[kbase + kk + 0] * wp[(kk + 0) * 100];
            a1 += hs[kbase + kk + 1] * wp[(kk + 1) * 100];
            a2 += hs[kbase + kk + 2] * wp[(kk + 2) * 100];
            a3 += hs[kbase + kk + 3] * wp[(kk + 3) * 100];
            a0 += hs[kbase + kk + 4] * wp[(kk + 4) * 100];
            a1 += hs[kbase + kk + 5] * wp[(kk + 5) * 100];
            a2 += hs[kbase + kk + 6] * wp[(kk + 6) * 100];
            a3 += hs[kbase + kk + 7] * wp[(kk + 7) * 100];
        }
        part[sp][o] = (a0 + a1) + (a2 + a3);
    }
    __syncthreads();
    if (tid < 100) {
        float d = b_dec[tid];
#pragma unroll
        for (int p = 0; p < 8; p++) d += part[p][tid];
        ds[tid] = fmaxf(d, 0.0f);
    }
    __syncthreads();
    if (tid < 2) {
        float a = b_fc[tid];
        for (int jj = 0; jj < 100; jj++) a += ds[jj] * W_fc[jj * 2 + tid];
        out[b * 2 + tid] = a;
    }
}

// ---------------- launch ----------------
extern "C" void kernel_launch(void* const* d_in, const int* in_sizes, int n_in,
                              void* d_out, int out_size) {
    const int* ids = (const int*)d_in[0];
    const float* emb = (const float*)d_in[1];
    const float* W_ih = (const float*)d_in[2];
    const float* W_hh = (const float*)d_in[3];
    const float* b_ih = (const float*)d_in[4];
    const float* b_hh = (const float*)d_in[5];
    const float* W_dec = (const float*)d_in[6];
    const float* b_dec = (const float*)d_in[7];
    const float* W_fc = (const float*)d_in[8];
    const float* b_fc = (const float*)d_in[9];
    float* out = (float*)d_out;

    static bool attr_set = false;
    if (!attr_set) {
        cudaFuncSetAttribute(gru_persist_kernel,
                             cudaFuncAttributeMaxDynamicSharedMemorySize, SMEM_BYTES);
        cudaFuncSetAttribute(gi_kernel,
                             cudaFuncAttributeMaxDynamicSharedMemorySize, GI_SMEM_BYTES);
        attr_set = true;
    }

    init_kernel<<<256, 256>>>();

    conv_emb_kernel<<<(VOCAB * H / 4 + 255) / 256, 256>>>(emb);
    conv_wih_kernel<<<(H * H3 / 4 + 255) / 256, 256>>>(W_ih);

    dim3 g1(24, 256);
    gi_kernel<<<g1, 256, GI_SMEM_BYTES>>>(ids);

    gru_persist_kernel<<<NCTA, 256, SMEM_BYTES>>>(W_hh, b_ih, b_hh);

    dec_kernel<<<64, 1024>>>(W_dec, b_dec, W_fc, b_fc, out);
}

// round 16
// speedup vs baseline: 2.3278x; 1.0008x over previous
#include <cuda_runtime.h>
#include <cstdint>

#define SEQ   512
#define BATCH 64
#define H     1024
#define H3    3072
#define VOCAB 32000
#define NCTA  128

// ---------------- device scratch (no cudaMalloc allowed) ----------------
__device__ float    g_gi[(size_t)SEQ * BATCH * H3];  // encoded @ W_ih (no bias)
__device__ float    g_h[BATCH * H];                  // final h (for dec only)
__device__ unsigned g_htf[2][BATCH * H];             // h ping-pong (tf32 bits)
__device__ unsigned g_bar;                           // grid barrier arrive counter
__device__ unsigned g_emb_tf[(size_t)VOCAB * H];     // emb pre-converted to tf32 bits
__device__ unsigned g_wih_tf[(size_t)H * H3];        // W_ih pre-converted to tf32 bits

// ---------------- helpers ----------------
__device__ __forceinline__ unsigned f2tf(float x) {
    unsigned r;
    asm("cvt.rna.tf32.f32 %0, %1;" : "=r"(r) : "f"(x));
    return r;
}

__device__ __forceinline__ void mma8(float c[4], const unsigned a[4],
                                     unsigned b0, unsigned b1) {
    asm volatile(
        "mma.sync.aligned.m16n8k8.row.col.f32.tf32.tf32.f32 "
        "{%0,%1,%2,%3},{%4,%5,%6,%7},{%8,%9},{%0,%1,%2,%3};"
        : "+f"(c[0]), "+f"(c[1]), "+f"(c[2]), "+f"(c[3])
        : "r"(a[0]), "r"(a[1]), "r"(a[2]), "r"(a[3]), "r"(b0), "r"(b1));
}

#define CP_ASYNC16(dst, src) \
    asm volatile("cp.async.cg.shared.global [%0], [%1], 16;" :: "r"(dst), "l"(src))
#define CP_COMMIT()  asm volatile("cp.async.commit_group;" ::: "memory")
#define CP_WAIT(n)   asm volatile("cp.async.wait_group %0;" :: "n"(n) : "memory")

__device__ __forceinline__ void red_add_release(unsigned* p, unsigned v) {
    asm volatile("red.release.gpu.global.add.u32 [%0], %1;"
                 :: "l"(p), "r"(v) : "memory");
}
__device__ __forceinline__ unsigned ld_acquire(const unsigned* p) {
    unsigned v;
    asm volatile("ld.acquire.gpu.u32 %0, [%1];" : "=r"(v) : "l"(p) : "memory");
    return v;
}

__device__ __forceinline__ float sigm(float x) { return 1.0f / (1.0f + __expf(-x)); }
__device__ __forceinline__ float tanh_fast(float x) {
    float e = __expf(2.0f * x);
    return 1.0f - 2.0f / (e + 1.0f);
}

// ---------------- K0b: pre-convert emb / W_ih to tf32 bits ----------------
__global__ void conv_emb_kernel(const float* __restrict__ emb) {
    size_t i = ((size_t)blockIdx.x * blockDim.x + threadIdx.x) * 4;
    if (i < (size_t)VOCAB * H) {
        float4 v = *(const float4*)(emb + i);
        uint4 o;
        o.x = f2tf(v.x); o.y = f2tf(v.y); o.z = f2tf(v.z); o.w = f2tf(v.w);
        *(uint4*)(g_emb_tf + i) = o;
    }
}
// also resets the grid-barrier counter each launch (replaces init_kernel)
__global__ void conv_wih_kernel(const float* __restrict__ W_ih) {
    if (blockIdx.x == 0 && threadIdx.x == 0) g_bar = 0u;
    size_t i = ((size_t)blockIdx.x * blockDim.x + threadIdx.x) * 4;
    if (i < (size_t)H * H3) {
        float4 v = *(const float4*)(W_ih + i);
        uint4 o;
        o.x = f2tf(v.x); o.y = f2tf(v.y); o.z = f2tf(v.z); o.w = f2tf(v.w);
        *(uint4*)(g_wih_tf + i) = o;
    }
}

// ---------------- K1: fused gather + gi GEMM (R15, untouched) ----------------
#define GI_AS_BUF (128 * 36)
#define GI_BS_BUF (32 * 136)
#define GI_SMEM_BYTES ((2 * GI_AS_BUF + 2 * GI_BS_BUF) * 4)

__global__ void __launch_bounds__(256) gi_kernel(const int* __restrict__ ids) {
    extern __shared__ unsigned gsm[];
    unsigned* As = gsm;                     // [2][128][36]
    unsigned* Bs = gsm + 2 * GI_AS_BUF;     // [2][32][136]
    __shared__ int ids_s[128];

    const int nb = blockIdx.x, mb = blockIdx.y;
    const int tid = threadIdx.x;
    const int w = tid >> 5, lane = tid & 31;
    const int wm = w >> 2, wn = w & 3;
    const int gid = lane >> 2, tig = lane & 3;

    if (tid < 128) ids_s[tid] = ids[mb * 128 + tid];
    __syncthreads();

    const unsigned as_smem = (unsigned)__cvta_generic_to_shared(As);
    const unsigned bs_smem = (unsigned)__cvta_generic_to_shared(Bs);

    const int a_row0 = tid >> 3;
    const int a_c0 = (tid & 7) * 4;
    const int b_r0 = tid >> 5;
    const int b_c0 = (tid & 31) * 4;

    auto stageA = [&](int buf, int kt) {
#pragma unroll
        for (int rep = 0; rep < 4; rep++) {
            int row = rep * 32 + a_row0;
            const unsigned* src = g_emb_tf + (size_t)ids_s[row] * H + kt + a_c0;
            CP_ASYNC16(as_smem + (unsigned)(buf * GI_AS_BUF + row * 36 + a_c0) * 4u, src);
        }
    };
    auto stageB = [&](int buf, int kt) {
#pragma unroll
        for (int rep = 0; rep < 4; rep++) {
            int r = rep * 8 + b_r0;
            const unsigned* src = g_wih_tf + (size_t)(kt + r) * H3 + nb * 128 + b_c0;
            CP_ASYNC16(bs_smem + (unsigned)(buf * GI_BS_BUF + r * 136 + b_c0) * 4u, src);
        }
    };

    float acc[4][4][4];
#pragma unroll
    for (int i = 0; i < 4; i++)
#pragma unroll
        for (int j = 0; j < 4; j++)
#pragma unroll
            for (int k = 0; k < 4; k++) acc[i][j][k] = 0.0f;

    stageA(0, 0); stageB(0, 0); CP_COMMIT();

    for (int t = 0; t < 32; t++) {
        const int buf = t & 1;
        __syncthreads();
        if (t < 31) {
            stageA(buf ^ 1, (t + 1) * 32);
            stageB(buf ^ 1, (t + 1) * 32);
            CP_COMMIT();
            CP_WAIT(1);
        } else {
            CP_WAIT(0);
        }
        __syncthreads();

        const unsigned* Ab = As + buf * GI_AS_BUF;
        const unsigned* Bb = Bs + buf * GI_BS_BUF;
#pragma unroll
        for (int ks = 0; ks < 32; ks += 8) {
            unsigned a[4][4];
#pragma unroll
            for (int mt = 0; mt < 4; mt++) {
                int rb = wm * 64 + mt * 16;
                a[mt][0] = Ab[(rb + gid) * 36 + ks + tig];
                a[mt][1] = Ab[(rb + gid + 8) * 36 + ks + tig];
                a[mt][2] = Ab[(rb + gid) * 36 + ks + tig + 4];
                a[mt][3] = Ab[(rb + gid + 8) * 36 + ks + tig + 4];
            }
#pragma unroll
            for (int nt = 0; nt < 4; nt++) {
                unsigned b0 = Bb[(ks + tig) * 136 + wn * 32 + nt * 8 + gid];
                unsigned b1 = Bb[(ks + tig + 4) * 136 + wn * 32 + nt * 8 + gid];
#pragma unroll
                for (int mt = 0; mt < 4; mt++) mma8(acc[mt][nt], a[mt], b0, b1);
            }
        }
    }

    size_t mrow0 = (size_t)mb * 128 + wm * 64;
    int colbase = nb * 128 + wn * 32;
#pragma unroll
    for (int mt = 0; mt < 4; mt++) {
        size_t m0 = mrow0 + mt * 16 + gid;
#pragma unroll
        for (int nt = 0; nt < 4; nt++) {
            int col = colbase + nt * 8 + tig * 2;
            *(float2*)(g_gi + m0 * H3 + col) = make_float2(acc[mt][nt][0], acc[mt][nt][1]);
            *(float2*)(g_gi + (m0 + 8) * H3 + col) = make_float2(acc[mt][nt][2], acc[mt][nt][3]);
        }
    }
}

// ---------------- K2: persistent GRU recurrence (R15 + analytic step 0) ----------------
#define WS_WORDS   (1024 * 24)
#define AS_WORDS_W 576
#define N_BUF      4
#define AS_WORDS   (8 * N_BUF * AS_WORDS_W)
#define GH_WORDS   (2 * 64 * 24)
#define SMEM_BYTES ((WS_WORDS + AS_WORDS + GH_WORDS) * 4)

__global__ void __launch_bounds__(256, 1) gru_persist_kernel(
    const float* __restrict__ W_hh,
    const float* __restrict__ b_ih,
    const float* __restrict__ b_hh) {
    extern __shared__ unsigned sm[];
    unsigned* Ws = sm;                                  // [1024][24]
    unsigned* As = sm + WS_WORDS;                       // [warp][4][16*36]
    float* ghs = (float*)(sm + WS_WORDS + AS_WORDS);    // [kh][64][24]

    const int c = blockIdx.x;
    const int tid = threadIdx.x;
    const int w = tid >> 5, lane = tid & 31;
    const int gid = lane >> 2, tig = lane & 3;
    const int mt = w & 3, kh = w >> 2;

    const unsigned as_base =
        (unsigned)__cvta_generic_to_shared(As + w * N_BUF * AS_WORDS_W);
    const int lr = lane >> 3;            // 0..3
    const int cw = (lane & 7) * 4;       // word col within 32

    // one-time W_hh slice preload (rna tf32)
    for (int idx = tid; idx < WS_WORDS; idx += 256) {
        int kk = idx / 24;
        int rem = idx - kk * 24;
        int g = rem >> 3, l = rem & 7;
        Ws[idx] = f2tf(W_hh[(size_t)kk * H3 + g * H + c * 8 + l]);
    }

    const int j = tid & 7;
    const int col = c * 8 + j;
    const int r0 = tid >> 3;
    const float bir = b_ih[col], biz = b_ih[H + col], bin = b_ih[2 * H + col];
    const float bhr = b_hh[col], bhz = b_hh[H + col], bhn = b_hh[2 * H + col];

    // register-resident hidden state
    float hp0 = 0.0f, hp1 = 0.0f;

    __syncthreads();

    // ---- step 0, analytic: h0 = 0 -> every mma product is exactly 0 -> gh = b_hh.
    //      Bit-identical to running the k-loop on a zero A operand. ----
    {
        const float* gi = g_gi;                  // s = 0
        const float* gp0 = gi + (size_t)r0 * H3;
        const float* gp1 = gi + (size_t)(r0 + 32) * H3;
        float ir0 = gp0[col], iz0 = gp0[H + col], in0 = gp0[2 * H + col];
        float ir1 = gp1[col], iz1 = gp1[H + col], in1 = gp1[2 * H + col];

        float r = sigm(ir0 + bir + bhr);
        float z = sigm(iz0 + biz + bhz);
        float n = tanh_fast(in0 + bin + r * bhn);
        hp0 = (1.0f - z) * n + z * hp0;
        g_htf[1][r0 * H + col] = f2tf(hp0);

        r = sigm(ir1 + bir + bhr);
        z = sigm(iz1 + biz + bhz);
        n = tanh_fast(in1 + bin + r * bhn);
        hp1 = (1.0f - z) * n + z * hp1;
        g_htf[1][(r0 + 32) * H + col] = f2tf(hp1);

        __syncthreads();
        if (tid == 0) {
            red_add_release(&g_bar, 1u);
            while (ld_acquire(&g_bar) < (unsigned)NCTA) {}
        }
        __syncthreads();
    }

    for (int s = 1; s < SEQ; s++) {
        const unsigned* htf  = g_htf[s & 1];
        unsigned*       htfo = g_htf[(s + 1) & 1];
        const float*    gi   = g_gi + (size_t)s * BATCH * H3;

        const unsigned* hsrc = htf + (mt * 16) * H + kh * 512 + cw;

        // stage pipeline: 3 tiles ahead
#pragma unroll
        for (int p = 0; p < 3; p++) {
            unsigned dst = as_base + (unsigned)(p * AS_WORDS_W) * 4u;
#pragma unroll
            for (int rep = 0; rep < 4; rep++) {
                int row = rep * 4 + lr;
                CP_ASYNC16(dst + (unsigned)(row * 36 + cw) * 4u, hsrc + row * H + p * 32);
            }
            CP_COMMIT();
        }

        // gate-phase gi prefetch (independent; hides latency behind mma)
        const float* gp0 = gi + (size_t)r0 * H3;
        const float* gp1 = gi + (size_t)(r0 + 32) * H3;
        float ir0 = gp0[col], iz0 = gp0[H + col], in0 = gp0[2 * H + col];
        float ir1 = gp1[col], iz1 = gp1[H + col], in1 = gp1[2 * H + col];

        float acc[3][4];
#pragma unroll
        for (int i = 0; i < 3; i++)
#pragma unroll
            for (int q = 0; q < 4; q++) acc[i][q] = 0.0f;

#pragma unroll
        for (int it = 0; it < 16; it++) {
            if (it < 13) {
                int p = it + 3;
                unsigned dst = as_base + (unsigned)((p & 3) * AS_WORDS_W) * 4u;
#pragma unroll
                for (int rep = 0; rep < 4; rep++) {
                    int row = rep * 4 + lr;
                    CP_ASYNC16(dst + (unsigned)(row * 36 + cw) * 4u,
                               hsrc + row * H + p * 32);
                }
                CP_COMMIT();
                CP_WAIT(3);
            } else if (it == 13) CP_WAIT(2);
            else if (it == 14) CP_WAIT(1);
            else CP_WAIT(0);
            __syncwarp();

            const unsigned* Ab = As + (w * N_BUF + (it & 3)) * AS_WORDS_W;
            const int kbase = kh * 512 + it * 32;
#pragma unroll
            for (int ks = 0; ks < 32; ks += 8) {
                unsigned a[4];
                a[0] = Ab[gid * 36 + ks + tig];
                a[1] = Ab[(gid + 8) * 36 + ks + tig];
                a[2] = Ab[gid * 36 + ks + tig + 4];
                a[3] = Ab[(gid + 8) * 36 + ks + tig + 4];
                const int kr = (kbase + ks + tig) * 24;
#pragma unroll
                for (int nt = 0; nt < 3; nt++) {
                    unsigned b0 = Ws[kr + nt * 8 + gid];
                    unsigned b1 = Ws[kr + 96 + nt * 8 + gid];
                    mma8(acc[nt], a, b0, b1);
                }
            }
        }

        // reduce the two k-halves via smem
        {
            int rr = mt * 16 + gid;
            float* gh = ghs + kh * (64 * 24);
#pragma unroll
            for (int nt = 0; nt < 3; nt++) {
                gh[rr * 24 + nt * 8 + tig * 2 + 0] = acc[nt][0];
                gh[rr * 24 + nt * 8 + tig * 2 + 1] = acc[nt][1];
                gh[(rr + 8) * 24 + nt * 8 + tig * 2 + 0] = acc[nt][2];
                gh[(rr + 8) * 24 + nt * 8 + tig * 2 + 1] = acc[nt][3];
            }
        }
        __syncthreads();

        // gate math: rows r0 and r0+32, column j (h carried in registers)
        const bool last = (s == SEQ - 1);
        {
            float ghr = ghs[r0 * 24 + j] + ghs[64 * 24 + r0 * 24 + j] + bhr;
            float ghz = ghs[r0 * 24 + 8 + j] + ghs[64 * 24 + r0 * 24 + 8 + j] + bhz;
            float ghn = ghs[r0 * 24 + 16 + j] + ghs[64 * 24 + r0 * 24 + 16 + j] + bhn;
            float r = sigm(ir0 + bir + ghr);
            float z = sigm(iz0 + biz + ghz);
            float n = tanh_fast(in0 + bin + r * ghn);
            hp0 = (1.0f - z) * n + z * hp0;
            if (!last) htfo[r0 * H + col] = f2tf(hp0);

            int r1 = r0 + 32;
            ghr = ghs[r1 * 24 + j] + ghs[64 * 24 + r1 * 24 + j] + bhr;
            ghz = ghs[r1 * 24 + 8 + j] + ghs[64 * 24 + r1 * 24 + 8 + j] + bhz;
            ghn = ghs[r1 * 24 + 16 + j] + ghs[64 * 24 + r1 * 24 + 16 + j] + bhn;
            r = sigm(ir1 + bir + ghr);
            z = sigm(iz1 + biz + ghz);
            n = tanh_fast(in1 + bin + r * ghn);
            hp1 = (1.0f - z) * n + z * hp1;
            if (!last) htfo[r1 * H + col] = f2tf(hp1);
        }

        if (!last) {
            // grid barrier: fire-and-forget arrival + direct counter poll
            __syncthreads();
            if (tid == 0) {
                unsigned tgt = (unsigned)(s + 1) * (unsigned)NCTA;
                red_add_release(&g_bar, 1u);
                while (ld_acquire(&g_bar) < tgt) {}
            }
            __syncthreads();
        }
    }

    // publish final h (fp32, full precision) for the dec kernel
    g_h[r0 * H + col] = hp0;
    g_h[(r0 + 32) * H + col] = hp1;
}

// ---------------- K3: decode + fc (8-way k-split, 1024 threads) ----------------
__global__ void __launch_bounds__(1024) dec_kernel(
    const float* __restrict__ W_dec, const float* __restrict__ b_dec,
    const float* __restrict__ W_fc, const float* __restrict__ b_fc,
    float* __restrict__ out) {
    int b = blockIdx.x;
    int tid = threadIdx.x;
    __shared__ float hs[H];
    __shared__ float part[8][100];
    __shared__ float ds[100];
    const float* hrow = g_h + b * H;
    for (int i = tid; i < H; i += 1024) hs[i] = hrow[i];
    __syncthreads();

    int o = tid & 127;
    int sp = tid >> 7;                    // 0..7 k-split
    if (o < 100) {
        float a0 = 0.0f, a1 = 0.0f, a2 = 0.0f, a3 = 0.0f;
        int kbase = sp * 128;
        const float* wp = W_dec + (size_t)kbase * 100 + o;
#pragma unroll 4
        for (int kk = 0; kk < 128; kk += 8) {
            a0 += hs[kbase + kk + 0] * wp[(kk + 0) * 100];
            a1 += hs[kbase + kk + 1] * wp[(kk + 1) * 100];
            a2 += hs[kbase + kk + 2] * wp[(kk + 2) * 100];
            a3 += hs[kbase + kk + 3] * wp[(kk + 3) * 100];
            a0 += hs[kbase + kk + 4] * wp[(kk + 4) * 100];
            a1 += hs[kbase + kk + 5] * wp[(kk + 5) * 100];
            a2 += hs[kbase + kk + 6] * wp[(kk + 6) * 100];
            a3 += hs[kbase + kk + 7] * wp[(kk + 7) * 100];
        }
        part[sp][o] = (a0 + a1) + (a2 + a3);
    }
    __syncthreads();
    if (tid < 100) {
        float d = b_dec[tid];
#pragma unroll
        for (int p = 0; p < 8; p++) d += part[p][tid];
        ds[tid] = fmaxf(d, 0.0f);
    }
    __syncthreads();
    if (tid < 2) {
        float a = b_fc[tid];
        for (int jj = 0; jj < 100; jj++) a += ds[jj] * W_fc[jj * 2 + tid];
        out[b * 2 + tid] = a;
    }
}

// ---------------- launch ----------------
extern "C" void kernel_launch(void* const* d_in, const int* in_sizes, int n_in,
                              void* d_out, int out_size) {
    const int* ids = (const int*)d_in[0];
    const float* emb = (const float*)d_in[1];
    const float* W_ih = (const float*)d_in[2];
    const float* W_hh = (const float*)d_in[3];
    const float* b_ih = (const float*)d_in[4];
    const float* b_hh = (const float*)d_in[5];
    const float* W_dec = (const float*)d_in[6];
    const float* b_dec = (const float*)d_in[7];
    const float* W_fc = (const float*)d_in[8];
    const float* b_fc = (const float*)d_in[9];
    float* out = (float*)d_out;

    static bool attr_set = false;
    if (!attr_set) {
        cudaFuncSetAttribute(gru_persist_kernel,
                             cudaFuncAttributeMaxDynamicSharedMemorySize, SMEM_BYTES);
        cudaFuncSetAttribute(gi_kernel,
                             cudaFuncAttributeMaxDynamicSharedMemorySize, GI_SMEM_BYTES);
        attr_set = true;
    }

    conv_emb_kernel<<<(VOCAB * H / 4 + 255) / 256, 256>>>(emb);
    conv_wih_kernel<<<(H * H3 / 4 + 255) / 256, 256>>>(W_ih);

    dim3 g1(24, 256);
    gi_kernel<<<g1, 256, GI_SMEM_BYTES>>>(ids);

    gru_persist_kernel<<<NCTA, 256, SMEM_BYTES>>>(W_hh, b_ih, b_hh);

    dec_kernel<<<64, 1024>>>(W_dec, b_dec, W_fc, b_fc, out);
}